// round 1
// baseline (speedup 1.0000x reference)
#include <cuda_runtime.h>
#include <cstdint>

// Problem constants (fixed shapes)
#define BZ 4
#define TN 4096
#define DN 1024
#define MN (BZ*TN)        // 16384 rows
#define SEG 256
#define NSEG (TN/SEG)     // 16

// ---------------------------------------------------------------------------
// Scratch (static __device__ arrays; no allocation allowed)
// ---------------------------------------------------------------------------
__device__ float g_xnorm[(size_t)MN*DN];
__device__ float g_la   [(size_t)MN*DN];
__device__ float g_bx   [(size_t)MN*DN];
__device__ float g_scan [(size_t)MN*DN];
__device__ float g_segL[BZ*NSEG*DN];
__device__ float g_segP[BZ*NSEG*DN];
__device__ float g_Lb  [BZ*NSEG*DN];
__device__ float g_sb  [BZ*NSEG*DN];

// ---------------------------------------------------------------------------
// Helpers
// ---------------------------------------------------------------------------
__device__ __forceinline__ void cp16(void* smem, const void* g) {
    uint32_t s = (uint32_t)__cvta_generic_to_shared(smem);
    asm volatile("cp.async.cg.shared.global [%0], [%1], 16;\n" :: "r"(s), "l"(g));
}
__device__ __forceinline__ void cp_commit() {
    asm volatile("cp.async.commit_group;\n");
}
__device__ __forceinline__ uint32_t f2tf(float f) {
    uint32_t u;
    asm volatile("cvt.rna.tf32.f32 %0, %1;\n" : "=r"(u) : "f"(f));
    return u;
}
__device__ __forceinline__ void mma_tf32(float* c, const uint32_t* a, const uint32_t* b) {
    asm volatile(
        "mma.sync.aligned.m16n8k8.row.col.f32.tf32.tf32.f32 "
        "{%0,%1,%2,%3}, {%4,%5,%6,%7}, {%8,%9}, {%0,%1,%2,%3};\n"
        : "+f"(c[0]), "+f"(c[1]), "+f"(c[2]), "+f"(c[3])
        : "r"(a[0]), "r"(a[1]), "r"(a[2]), "r"(a[3]),
          "r"(b[0]), "r"(b[1]));
}

// ---------------------------------------------------------------------------
// Kernel 1: LayerNorm over last dim (D=1024), one block per row
// ---------------------------------------------------------------------------
__global__ __launch_bounds__(256) void ln_kernel(
    const float* __restrict__ x, const float* __restrict__ w,
    const float* __restrict__ b, float* __restrict__ y)
{
    __shared__ float rbuf[8];
    __shared__ float stat[2];
    const int row = blockIdx.x;
    const int tid = threadIdx.x;

    const float4* xr = (const float4*)(x + (size_t)row * DN);
    float4 v = xr[tid];

    float s = v.x + v.y + v.z + v.w;
    #pragma unroll
    for (int o = 16; o > 0; o >>= 1) s += __shfl_xor_sync(0xffffffffu, s, o);
    if ((tid & 31) == 0) rbuf[tid >> 5] = s;
    __syncthreads();
    if (tid == 0) {
        float t = 0.f;
        #pragma unroll
        for (int i = 0; i < 8; i++) t += rbuf[i];
        stat[0] = t * (1.0f / DN);
    }
    __syncthreads();
    const float mu = stat[0];

    float dx0 = v.x - mu, dx1 = v.y - mu, dx2 = v.z - mu, dx3 = v.w - mu;
    float s2 = dx0*dx0 + dx1*dx1 + dx2*dx2 + dx3*dx3;
    #pragma unroll
    for (int o = 16; o > 0; o >>= 1) s2 += __shfl_xor_sync(0xffffffffu, s2, o);
    __syncthreads();   // make sure previous rbuf reads are done
    if ((tid & 31) == 0) rbuf[tid >> 5] = s2;
    __syncthreads();
    if (tid == 0) {
        float t = 0.f;
        #pragma unroll
        for (int i = 0; i < 8; i++) t += rbuf[i];
        stat[1] = rsqrtf(t * (1.0f / DN) + 1e-5f);
    }
    __syncthreads();
    const float rs = stat[1];

    const float4 w4 = ((const float4*)w)[tid];
    const float4 b4 = ((const float4*)b)[tid];
    float4 o4;
    o4.x = dx0 * rs * w4.x + b4.x;
    o4.y = dx1 * rs * w4.y + b4.y;
    o4.z = dx2 * rs * w4.z + b4.z;
    o4.w = dx3 * rs * w4.w + b4.w;
    ((float4*)(y + (size_t)row * DN))[tid] = o4;
}

// ---------------------------------------------------------------------------
// GEMM: C[m,n] = sum_k A[m,k]*W[n,k]   (A row-major MxK, W row-major NxK)
// 128x128 block tile, BK=32, TF32 mma.sync m16n8k8, cp.async double buffer.
// EPI==1: alpha/log_alpha/beta_x epilogue.   EPI==2: tanh + residual.
// ---------------------------------------------------------------------------
#define SROW 36                 // padded smem row stride (floats)
#define BUF_F (128*SROW)        // floats per buffer
#define GEMM_SMEM_BYTES (4*BUF_F*4)   // 2 A bufs + 2 B bufs

template<int EPI>
__global__ __launch_bounds__(256) void gemm_kernel(
    const float* __restrict__ A, const float* __restrict__ W,
    const float* __restrict__ bias,
    const float* __restrict__ sc1,   // alpha_bias (EPI==1)
    const float* __restrict__ sc2,   // beta_scale (EPI==1)
    const float* __restrict__ Xref,  // x_norm (EPI==1) or residual x (EPI==2)
    float* __restrict__ O1,          // log_alpha (EPI==1) or final out (EPI==2)
    float* __restrict__ O2)          // beta_x (EPI==1) or unused
{
    extern __shared__ float sm[];
    float* As = sm;                 // [2][128][SROW]
    float* Bs = sm + 2*BUF_F;       // [2][128][SROW]

    const int tid  = threadIdx.x;
    const int m0   = blockIdx.y * 128;
    const int n0   = blockIdx.x * 128;
    const int lane = tid & 31;
    const int warp = tid >> 5;
    const int wm   = (warp & 1) * 64;
    const int wn   = (warp >> 1) * 32;
    const int grp  = lane >> 2;
    const int thr  = lane & 3;

    float acc[4][4][4];
    #pragma unroll
    for (int i = 0; i < 4; i++)
        #pragma unroll
        for (int j = 0; j < 4; j++)
            #pragma unroll
            for (int r = 0; r < 4; r++) acc[i][j][r] = 0.f;

    const int KT = DN / 32;         // 32 k-chunks
    const int lr = tid >> 3;        // 0..31 (row within group of 32)
    const int lc = (tid & 7) * 4;   // float col offset (16B chunk)

    auto issue = [&](int kt, int buf) {
        const float* Ag = A + (size_t)(m0 + lr) * DN + kt*32 + lc;
        const float* Wg = W + (size_t)(n0 + lr) * DN + kt*32 + lc;
        float* Asb = As + buf * BUF_F;
        float* Bsb = Bs + buf * BUF_F;
        #pragma unroll
        for (int i = 0; i < 4; i++) {
            cp16(Asb + (lr + i*32)*SROW + lc, Ag + (size_t)i*32*DN);
            cp16(Bsb + (lr + i*32)*SROW + lc, Wg + (size_t)i*32*DN);
        }
        cp_commit();
    };

    issue(0, 0);
    issue(1, 1);

    for (int kt = 0; kt < KT; ++kt) {
        if (kt + 1 < KT) asm volatile("cp.async.wait_group 1;\n");
        else             asm volatile("cp.async.wait_group 0;\n");
        __syncthreads();

        const float* Asb = As + (kt & 1) * BUF_F;
        const float* Bsb = Bs + (kt & 1) * BUF_F;

        #pragma unroll
        for (int ks = 0; ks < 4; ks++) {
            uint32_t af[4][4];
            uint32_t bfr[4][2];
            #pragma unroll
            for (int i = 0; i < 4; i++) {
                const float* ap = Asb + (wm + i*16 + grp)*SROW + ks*8 + thr;
                af[i][0] = f2tf(ap[0]);
                af[i][1] = f2tf(ap[8*SROW]);
                af[i][2] = f2tf(ap[4]);
                af[i][3] = f2tf(ap[8*SROW + 4]);
            }
            #pragma unroll
            for (int j = 0; j < 4; j++) {
                const float* bp = Bsb + (wn + j*8 + grp)*SROW + ks*8 + thr;
                bfr[j][0] = f2tf(bp[0]);
                bfr[j][1] = f2tf(bp[4]);
            }
            #pragma unroll
            for (int i = 0; i < 4; i++)
                #pragma unroll
                for (int j = 0; j < 4; j++)
                    mma_tf32(&acc[i][j][0], &af[i][0], &bfr[j][0]);
        }
        __syncthreads();
        if (kt + 2 < KT) issue(kt + 2, kt & 1);
    }

    // ---------------- Epilogue ----------------
    if (EPI == 1) {
        const float ab = sc1[0];
        const float bscale = sc2[0];
        #pragma unroll
        for (int i = 0; i < 4; i++) {
            #pragma unroll
            for (int j = 0; j < 4; j++) {
                const int col = n0 + wn + j*8 + thr*2;
                const float b0 = __ldg(bias + col);
                const float b1 = __ldg(bias + col + 1);
                #pragma unroll
                for (int h = 0; h < 2; h++) {
                    const int row = m0 + wm + i*16 + grp + h*8;
                    const float z0 = acc[i][j][2*h+0] + b0 + ab;
                    const float z1 = acc[i][j][2*h+1] + b1 + ab;
                    const float a0 = 1.0f / (1.0f + expf(-z0));
                    const float a1 = 1.0f / (1.0f + expf(-z1));
                    const float2 xn = *(const float2*)(Xref + (size_t)row*DN + col);
                    float2 lav, bxv;
                    lav.x = logf(a0 + 1e-8f);
                    lav.y = logf(a1 + 1e-8f);
                    bxv.x = bscale * (1.0f - a0) * xn.x;
                    bxv.y = bscale * (1.0f - a1) * xn.y;
                    *(float2*)(O1 + (size_t)row*DN + col) = lav;
                    *(float2*)(O2 + (size_t)row*DN + col) = bxv;
                }
            }
        }
    } else {
        #pragma unroll
        for (int i = 0; i < 4; i++) {
            #pragma unroll
            for (int j = 0; j < 4; j++) {
                const int col = n0 + wn + j*8 + thr*2;
                const float b0 = __ldg(bias + col);
                const float b1 = __ldg(bias + col + 1);
                #pragma unroll
                for (int h = 0; h < 2; h++) {
                    const int row = m0 + wm + i*16 + grp + h*8;
                    const float g0 = tanhf(acc[i][j][2*h+0] + b0);
                    const float g1 = tanhf(acc[i][j][2*h+1] + b1);
                    const float2 res = *(const float2*)(Xref + (size_t)row*DN + col);
                    float2 o;
                    o.x = g0 * 0.05f + res.x;
                    o.y = g1 * 0.05f + res.y;
                    *(float2*)(O1 + (size_t)row*DN + col) = o;
                }
            }
        }
    }
}

// ---------------------------------------------------------------------------
// Scan phase 1: per (b, seg, d): segment sum of log_alpha and
//               P = sum_t beta_x[t] * exp(local_cumsum_incl[t])
// ---------------------------------------------------------------------------
__global__ __launch_bounds__(128) void scan_seg1(
    const float* __restrict__ la, const float* __restrict__ bx,
    float* __restrict__ segL, float* __restrict__ segP)
{
    const int d = blockIdx.x * 128 + threadIdx.x;
    const int s = blockIdx.y;
    const int b = blockIdx.z;
    int idx = (b*TN + s*SEG) * DN + d;
    float L = 0.f, P = 0.f;
    #pragma unroll 4
    for (int t = 0; t < SEG; t++) {
        const float l = la[idx];
        const float x = bx[idx];
        L += l;
        P += x * expf(L);
        idx += DN;
    }
    const int o = (b*NSEG + s) * DN + d;
    segL[o] = L;
    segP[o] = P;
}

// ---------------------------------------------------------------------------
// Scan phase 2: per (b, d): exclusive combine across the 16 segments.
// m = log_alpha[b, t=0, d] (cumsum is non-increasing -> max is first element).
// ---------------------------------------------------------------------------
__global__ __launch_bounds__(256) void scan_seg2(
    const float* __restrict__ la,
    const float* __restrict__ segL, const float* __restrict__ segP,
    float* __restrict__ Lb, float* __restrict__ sb)
{
    const int idx = blockIdx.x * 256 + threadIdx.x;   // 0..4095
    const int b = idx >> 10;
    const int d = idx & (DN - 1);
    const float m = la[(size_t)b * TN * DN + d];
    float Lex = 0.f, ss = 0.f;
    #pragma unroll
    for (int s = 0; s < NSEG; s++) {
        const int o = (b*NSEG + s) * DN + d;
        Lb[o] = Lex - m;
        sb[o] = ss;
        ss  += segP[o] * expf(Lex - m);
        Lex += segL[o];
    }
}

// ---------------------------------------------------------------------------
// Scan phase 3: final streaming pass producing output = s_star/(scale+eps)
// ---------------------------------------------------------------------------
__global__ __launch_bounds__(128) void scan_seg3(
    const float* __restrict__ la, const float* __restrict__ bx,
    const float* __restrict__ Lb, const float* __restrict__ sb,
    float* __restrict__ out)
{
    const int d = blockIdx.x * 128 + threadIdx.x;
    const int s = blockIdx.y;
    const int b = blockIdx.z;
    const int o = (b*NSEG + s) * DN + d;
    float L  = Lb[o];      // = (exclusive prefix of log_alpha) - m
    float ss = sb[o];
    int idx = (b*TN + s*SEG) * DN + d;
    #pragma unroll 4
    for (int t = 0; t < SEG; t++) {
        const float l = la[idx];
        const float x = bx[idx];
        L += l;
        const float sc = expf(L);
        ss += x * sc;
        out[idx] = ss / (sc + 1e-8f);
        idx += DN;
    }
}

// ---------------------------------------------------------------------------
// Launch
// ---------------------------------------------------------------------------
extern "C" void kernel_launch(void* const* d_in, const int* in_sizes, int n_in,
                              void* d_out, int out_size)
{
    const float* x    = (const float*)d_in[0];
    const float* ln_w = (const float*)d_in[1];
    const float* ln_b = (const float*)d_in[2];
    const float* Wf   = (const float*)d_in[3];
    const float* bf   = (const float*)d_in[4];
    const float* Wr   = (const float*)d_in[5];
    const float* br   = (const float*)d_in[6];
    const float* ab   = (const float*)d_in[7];
    const float* bs   = (const float*)d_in[8];
    float* out = (float*)d_out;

    float *p_xnorm, *p_la, *p_bx, *p_scan, *p_segL, *p_segP, *p_Lb, *p_sb;
    cudaGetSymbolAddress((void**)&p_xnorm, g_xnorm);
    cudaGetSymbolAddress((void**)&p_la,    g_la);
    cudaGetSymbolAddress((void**)&p_bx,    g_bx);
    cudaGetSymbolAddress((void**)&p_scan,  g_scan);
    cudaGetSymbolAddress((void**)&p_segL,  g_segL);
    cudaGetSymbolAddress((void**)&p_segP,  g_segP);
    cudaGetSymbolAddress((void**)&p_Lb,    g_Lb);
    cudaGetSymbolAddress((void**)&p_sb,    g_sb);

    cudaFuncSetAttribute(gemm_kernel<1>, cudaFuncAttributeMaxDynamicSharedMemorySize, GEMM_SMEM_BYTES);
    cudaFuncSetAttribute(gemm_kernel<2>, cudaFuncAttributeMaxDynamicSharedMemorySize, GEMM_SMEM_BYTES);

    // 1) LayerNorm
    ln_kernel<<<MN, 256>>>(x, ln_w, ln_b, p_xnorm);

    // 2) GEMM1: z = x_norm @ Wf^T + bf + alpha_bias; fused sigmoid/log/beta epilogue
    dim3 ggrid(DN/128, MN/128);
    gemm_kernel<1><<<ggrid, 256, GEMM_SMEM_BYTES>>>(
        p_xnorm, Wf, bf, ab, bs, p_xnorm, p_la, p_bx);

    // 3) Segmented scan over T
    dim3 sgrid(DN/128, NSEG, BZ);
    scan_seg1<<<sgrid, 128>>>(p_la, p_bx, p_segL, p_segP);
    scan_seg2<<<(BZ*DN)/256, 256>>>(p_la, p_segL, p_segP, p_Lb, p_sb);
    scan_seg3<<<sgrid, 128>>>(p_la, p_bx, p_Lb, p_sb, p_scan);

    // 4) GEMM2: tanh(out_scan @ Wr^T + br)*0.05 + x
    gemm_kernel<2><<<ggrid, 256, GEMM_SMEM_BYTES>>>(
        p_scan, Wr, br, nullptr, nullptr, x, out, nullptr);
}